// round 16
// baseline (speedup 1.0000x reference)
#include <cuda_runtime.h>
#include <math.h>
#include <stdint.h>

// Problem constants (from reference)
#define B   256
#define F   2048
#define C   16384
#define NS  65536
#define P   8
#define NN  32
#define P_MARGIN 0.1f
#define N_MARGIN 0.1f
#define W_H 10.0

// tf32 truncation bias compensation: 2*ln2*2^-11
#define TF32_COMP 1.000677f
#define LSE_SHIFT 8.0f
#define NCAND 40            // 8 ppairs + 32 npairs

// ---------------- device scratch (no allocations allowed) ----------------
__device__ float    g_partial[B * 128];   // [row][ctaX] partial sums of exp(x-8)
__device__ double   g_hp_sum;
__device__ double   g_hn_sum;
__device__ double   g_bu_sum;
__device__ unsigned g_ticket;
__device__ unsigned g_done;               // grid barrier arrival counter

__device__ __forceinline__ uint32_t smem_u32(const void* p) {
    uint32_t a;
    asm("{ .reg .u64 t; cvta.to.shared.u64 t, %1; cvt.u32.u64 %0, t; }" : "=r"(a) : "l"(p));
    return a;
}
__device__ __forceinline__ uint32_t swz128(uint32_t x) { return x ^ ((x >> 3) & 0x70); }
__device__ __forceinline__ void cpasync16(uint32_t s, const void* g) {
    asm volatile("cp.async.cg.shared.global [%0], [%1], 16;" :: "r"(s), "l"(g));
}

// =====================================================================
//  ONE persistent kernel:
//  Phase A: tf32 mma.sync GEMM (256x128x64 CTA tile, 64x64 warp tile,
//           2-stage GBK=64 pipeline — identical to round-15 mainloop)
//           + logits store + per-CTA exp-sum partials.
//  Phase B: software grid barrier (128 CTAs = exactly one co-resident
//           wave at 192 KB smem/CTA -> deadlock-free).
//  Phase C: each CTA processes rows 2b and 2b+1: lse from partials +
//           on-demand pair dots + mining; last row (ticket) writes loss.
//  Scratch for phase C carved from the 192 KB dynamic smem.
//  NOTE: outp is only 4-byte aligned (out + 1) -> scalar stores ONLY.
// =====================================================================
#define GBM 256
#define GBN 128
#define GBK 64
#define A_HALF  (GBM * 128)              // 32 KB (one k-half of A)
#define B_HALF  (GBN * 128)              // 16 KB
#define A_BYTES (2 * A_HALF)             // 64 KB
#define B_BYTES (2 * B_HALF)             // 32 KB
#define STG_B   (A_BYTES + B_BYTES)      // 96 KB
#define GEMM_SMEM (2 * STG_B)            // 192 KB
#define NCHUNK  (F / GBK)                // 32

// phase-C shared-memory overlay (fits easily in 192 KB)
struct TailSmem {
    float xi[F];              // 8 KB: row i of inputs
    int   idx[B];
    float red[128];
    int   m[NCAND];
    int   v[NCAND];
    float dij[NCAND + 1];
    float djj[NCAND + 1];
    float tn[NN];
    float tp;
    float lse;
    float ps[P + 1];
    int   pm[P + 1];
    float ns[2 * NN];
    int   nm[2 * NN];
};

__device__ __forceinline__ void ldsm_x4(uint32_t addr, uint32_t* r) {
    asm volatile("ldmatrix.sync.aligned.m8n8.x4.shared.b16 {%0,%1,%2,%3}, [%4];"
                 : "=r"(r[0]), "=r"(r[1]), "=r"(r[2]), "=r"(r[3]) : "r"(addr));
}

__device__ __forceinline__ void load_stage_g(uint32_t sbase, int s, int chunk,
                                             const float* __restrict__ inp,
                                             const float* __restrict__ Vm,
                                             int nbase, int tid) {
    const int kbase = chunk * GBK;
    const uint32_t sA = sbase + s * STG_B;
    const uint32_t sB = sA + A_BYTES;
#pragma unroll
    for (int i = 0; i < 16; i++) {           // A: 256 rows x 64 floats
        int id = tid + i * 256;
        int row = id >> 4, c4 = id & 15;
        uint32_t half = (uint32_t)(c4 >> 3) * A_HALF;
        int c4in = c4 & 7;
        cpasync16(sA + half + swz128(row * 128 + c4in * 16),
                  inp + (size_t)row * F + kbase + c4 * 4);
    }
#pragma unroll
    for (int i = 0; i < 8; i++) {            // B: 128 rows x 64 floats
        int id = tid + i * 256;
        int row = id >> 4, c4 = id & 15;
        uint32_t half = (uint32_t)(c4 >> 3) * B_HALF;
        int c4in = c4 & 7;
        cpasync16(sB + half + swz128(row * 128 + c4in * 16),
                  Vm + (size_t)(nbase + row) * F + kbase + c4 * 4);
    }
}

// phase-C per-row worker (256 threads)
__device__ void do_row(int row, TailSmem* T,
                       const float* __restrict__ outputs,
                       const float* __restrict__ inputs,
                       const int* __restrict__ targets,
                       const int* __restrict__ ppairs,
                       const int* __restrict__ npairs,
                       const int* __restrict__ cluster,
                       float* __restrict__ out, int offset,
                       int tid, int lane, int warp) {
    const float* x = outputs + (size_t)row * C;

    // phase 1: stage row i + partials
    {
        const float4* xi4 = (const float4*)(inputs + (size_t)row * F);
        float4* s4 = (float4*)T->xi;
        s4[tid] = xi4[tid];
        s4[tid + 256] = xi4[tid + 256];
    }
    if (tid < 128) T->red[tid] = g_partial[(size_t)row * 128 + tid];
    __syncthreads();

    // phase 2: lse (warp 0) | candidate search | table logits
    if (tid < 32) {
        float s = T->red[lane] + T->red[lane + 32] + T->red[lane + 64] + T->red[lane + 96];
#pragma unroll
        for (int st = 16; st > 0; st >>= 1)
            s += __shfl_xor_sync(0xFFFFFFFFu, s, st);
        if (lane == 0) T->lse = logf(s) + LSE_SHIFT;
    } else if (tid >= 32 && tid < 32 + NCAND) {
        int c = tid - 32;
        int v = (c < P) ? ppairs[row * P + c] : npairs[row * NN + (c - P)];
        int idx = -1;
        for (int j = 0; j < B; j++)
            if (T->idx[j] == v) { idx = j; break; }
        T->v[c] = v;
        T->m[c] = (idx >= 0 && v >= 0) ? idx : -1;
    } else if (tid >= 96 && tid < 96 + NN) {
        int k = tid - 96;
        int v = npairs[row * NN + k];
        int vc = v > 0 ? v : 0;
        T->tn[k] = x[cluster[vc]];
    } else if (tid == 96 + NN) {
        T->tp = x[targets[row]];
    }
    __syncthreads();

    // phase 3: warp-per-pair dot products (8 warps)
    for (int c = warp; c <= NCAND; c += 8) {
        int j = (c == NCAND) ? row : T->m[c];
        if (j < 0) { if (lane == 0) { T->dij[c] = 0.f; T->djj[c] = 1.f; } continue; }
        const float4* xj4 = (const float4*)(inputs + (size_t)j * F);
        const float4* xi4 = (const float4*)T->xi;
        float sij = 0.f, sjj = 0.f;
#pragma unroll 4
        for (int t = lane; t < F / 4; t += 32) {
            float4 bv = xj4[t];
            float4 av = xi4[t];
            sij += av.x * bv.x + av.y * bv.y + av.z * bv.z + av.w * bv.w;
            sjj += bv.x * bv.x + bv.y * bv.y + bv.z * bv.z + bv.w * bv.w;
        }
#pragma unroll
        for (int st = 16; st > 0; st >>= 1) {
            sij += __shfl_xor_sync(0xFFFFFFFFu, sij, st);
            sjj += __shfl_xor_sync(0xFFFFFFFFu, sjj, st);
        }
        if (lane == 0) { T->dij[c] = sij; T->djj[c] = sjj; }
    }
    __syncthreads();

    // phase 4: candidate sims
    {
        const float inorm = sqrtf(T->djj[NCAND]);
        if (tid < P) {
            int idx = T->m[tid];
            T->pm[tid] = (idx >= 0);
            T->ps[tid] = (idx >= 0) ? T->dij[tid] / (inorm * sqrtf(T->djj[tid])) : 0.f;
        } else if (tid == P) {
            float tp = T->tp / inorm;
            T->ps[P] = tp;
            T->pm[P] = (tp != 0.0f);
        } else if (tid >= 32 && tid < 32 + NN) {
            int k = tid - 32;
            int c = P + k;
            int idx = T->m[c];
            T->nm[k] = (idx >= 0);
            T->ns[k] = (idx >= 0) ? T->dij[c] / (inorm * sqrtf(T->djj[c])) : 0.f;
        } else if (tid >= 64 && tid < 64 + NN) {
            int k = tid - 64;
            float tn = T->tn[k] / inorm;
            T->ns[NN + k] = tn;
            T->nm[NN + k] = ((T->v[P + k] >= 0) && (tn != 0.0f));
        }
    }
    __syncthreads();

    // phase 5: warp-0 mining via shfl reductions
    if (tid < 32) {
        int m0 = T->nm[lane], m1 = T->nm[lane + 32];
        float v0 = T->ns[lane], v1 = T->ns[lane + 32];
        float nmax = fmaxf(m0 ? v0 : -INFINITY, m1 ? v1 : -INFINITY);
#pragma unroll
        for (int st = 16; st > 0; st >>= 1)
            nmax = fmaxf(nmax, __shfl_xor_sync(0xFFFFFFFFu, nmax, st));
        int anyn = __ballot_sync(0xFFFFFFFFu, m0 || m1) != 0;
        float p_thrd = (anyn ? nmax : -3.0f) + P_MARGIN;

        int pmv = (lane < P + 1) ? T->pm[lane] : 0;
        float pv = pmv ? T->ps[lane] : INFINITY;
        float pmin = pv;
#pragma unroll
        for (int st = 16; st > 0; st >>= 1)
            pmin = fminf(pmin, __shfl_xor_sync(0xFFFFFFFFu, pmin, st));
        int anyp = __ballot_sync(0xFFFFFFFFu, pmv) != 0;
        float n_thrd = (anyp ? pmin : 3.0f) - N_MARGIN;

        double hp = 0.0, hn = 0.0;
        if (pmv && pv < p_thrd) hp = (double)expf(-2.0f * (pv - 0.5f));
        if (m0 && v0 > n_thrd && v0 < 0.999999f) hn += (double)expf(50.0f * (v0 - 0.5f));
        if (m1 && v1 > n_thrd && v1 < 0.999999f) hn += (double)expf(50.0f * (v1 - 0.5f));
#pragma unroll
        for (int st = 16; st > 0; st >>= 1) {
            hp += __shfl_xor_sync(0xFFFFFFFFu, hp, st);
            hn += __shfl_xor_sync(0xFFFFFFFFu, hn, st);
        }

        if (lane == 0) {
            if (hp != 0.0) atomicAdd(&g_hp_sum, hp);
            if (hn != 0.0) atomicAdd(&g_hn_sum, hn);
            atomicAdd(&g_bu_sum, (double)(T->lse - T->tp));
            __threadfence();
            unsigned ticket = atomicAdd(&g_ticket, 1u);
            if (ticket == B - 1) {
                double bu = g_bu_sum / (double)B;
                double hp_loss = (g_hp_sum > 0.0) ? 0.5 * log1p(g_hp_sum) : 0.0;
                double hn_loss = (g_hn_sum > 0.0) ? (1.0 / 50.0) * log1p(g_hn_sum) : 0.0;
                float loss = (float)(bu + W_H * (hp_loss + hn_loss));
                for (int i = 0; i < offset; i++) out[i] = loss;
            }
        }
    }
}

__global__ __launch_bounds__(256, 1) void fused_kernel(
        const float* __restrict__ inp,       // [B, F]
        const float* __restrict__ Vm,        // [C, F]
        float* __restrict__ outp,            // [B, C] (4-byte aligned only!)
        const int* __restrict__ targets,
        const int* __restrict__ ppairs,
        const int* __restrict__ npairs,
        const int* __restrict__ indexs,
        const int* __restrict__ cluster,
        float* __restrict__ out, int offset) {
    extern __shared__ __align__(1024) char smem[];
    const uint32_t sbase = smem_u32(smem);
    const int tid = threadIdx.x;
    const int nbase = blockIdx.x * GBN;
    const int lane = tid & 31;
    const int warp = tid >> 5;
    const int wm = warp >> 1;                // 0..3 -> m offset 64*wm
    const int wn = warp & 1;                 // 0..1 -> n offset 64*wn

    // reset global accumulators + barrier (one wave; increments happen
    // only after ~90us of gemm work, reset lands within ~us of launch)
    if (blockIdx.x == 0 && tid == 0) {
        g_hp_sum = 0.0;
        g_hn_sum = 0.0;
        g_bu_sum = 0.0;
        g_ticket = 0u;
        g_done = 0u;
    }

    float acc[4][8][4];
#pragma unroll
    for (int mi = 0; mi < 4; mi++)
#pragma unroll
        for (int ni = 0; ni < 8; ni++)
#pragma unroll
            for (int j = 0; j < 4; j++) acc[mi][ni][j] = 0.f;

    // prologue: 1 chunk in flight
    load_stage_g(sbase, 0, 0, inp, Vm, nbase, tid);
    asm volatile("cp.async.commit_group;" ::: "memory");

    // per-lane ldmatrix row components
    const int a_row_lo = (lane & 8) + (lane & 7);
    const int a_chunk_off = lane >> 4;
    const int b_row8 = lane & 7;
    const int b_ni_off = lane >> 4;
    const int b_chunk_off = (lane >> 3) & 1;

    for (int c = 0; c < NCHUNK; c++) {
        asm volatile("cp.async.wait_group 0;" ::: "memory");
        __syncthreads();

        if (c + 1 < NCHUNK) {
            load_stage_g(sbase, (c + 1) & 1, c + 1, inp, Vm, nbase, tid);
            asm volatile("cp.async.commit_group;" ::: "memory");
        }

        const uint32_t aS = sbase + (c & 1) * STG_B;
        const uint32_t bS = aS + A_BYTES;
#pragma unroll
        for (int ks = 0; ks < 8; ks++) {
            const uint32_t aSh = aS + (uint32_t)(ks >> 2) * A_HALF;
            const uint32_t bSh = bS + (uint32_t)(ks >> 2) * B_HALF;
            const int ksl = ks & 3;
            uint32_t af[4][4];
#pragma unroll
            for (int mi = 0; mi < 4; mi++) {
                int row = wm * 64 + mi * 16 + a_row_lo;
                int chunk = ksl * 2 + a_chunk_off;
                uint32_t addr = aSh + row * 128 + (((uint32_t)(chunk ^ (row & 7))) << 4);
                ldsm_x4(addr, af[mi]);
            }
            uint32_t bf[8][2];
#pragma unroll
            for (int bp = 0; bp < 4; bp++) {
                int ni = bp * 2 + b_ni_off;
                int row = wn * 64 + ni * 8 + b_row8;
                int chunk = ksl * 2 + b_chunk_off;
                uint32_t addr = bSh + row * 128 + (((uint32_t)(chunk ^ (row & 7))) << 4);
                uint32_t r[4];
                ldsm_x4(addr, r);
                bf[bp * 2][0] = r[0];     bf[bp * 2][1] = r[1];
                bf[bp * 2 + 1][0] = r[2]; bf[bp * 2 + 1][1] = r[3];
            }
            // no cvt: HW truncates fp32 -> tf32; compensated in epilogue
#pragma unroll
            for (int mi = 0; mi < 4; mi++)
#pragma unroll
                for (int ni = 0; ni < 8; ni++) {
                    asm volatile(
                        "mma.sync.aligned.m16n8k8.row.col.f32.tf32.tf32.f32 "
                        "{%0,%1,%2,%3}, {%4,%5,%6,%7}, {%8,%9}, {%0,%1,%2,%3};"
                        : "+f"(acc[mi][ni][0]), "+f"(acc[mi][ni][1]),
                          "+f"(acc[mi][ni][2]), "+f"(acc[mi][ni][3])
                        : "r"(af[mi][0]), "r"(af[mi][1]),
                          "r"(af[mi][2]), "r"(af[mi][3]),
                          "r"(bf[ni][0]), "r"(bf[ni][1]));
                }
        }
    }

    // ---- epilogue 1: compensated logits -> gmem (scalar stores, 4B align) ----
#pragma unroll
    for (int mi = 0; mi < 4; mi++) {
#pragma unroll
        for (int ni = 0; ni < 8; ni++) {
            int m = wm * 64 + mi * 16 + (lane >> 2);
            int n = nbase + wn * 64 + ni * 8 + 2 * (lane & 3);
            float* p0 = outp + (size_t)m * C + n;
            float* p1 = outp + (size_t)(m + 8) * C + n;
#pragma unroll
            for (int j = 0; j < 4; j++) acc[mi][ni][j] *= TF32_COMP;
            p0[0] = acc[mi][ni][0];
            p0[1] = acc[mi][ni][1];
            p1[0] = acc[mi][ni][2];
            p1[1] = acc[mi][ni][3];
        }
    }

    // ---- epilogue 2: per-CTA exp-sum partials (deterministic) ----
    __syncthreads();                         // all ldsm reads of smem done
    float* rs = (float*)smem;                // rs[2][256] (wn-sliced row sums)
#pragma unroll
    for (int mi = 0; mi < 4; mi++) {
        float eA = 0.f, eB = 0.f;
#pragma unroll
        for (int ni = 0; ni < 8; ni++) {
            eA += __expf(acc[mi][ni][0] - LSE_SHIFT) + __expf(acc[mi][ni][1] - LSE_SHIFT);
            eB += __expf(acc[mi][ni][2] - LSE_SHIFT) + __expf(acc[mi][ni][3] - LSE_SHIFT);
        }
        eA += __shfl_xor_sync(0xFFFFFFFFu, eA, 1);
        eA += __shfl_xor_sync(0xFFFFFFFFu, eA, 2);
        eB += __shfl_xor_sync(0xFFFFFFFFu, eB, 1);
        eB += __shfl_xor_sync(0xFFFFFFFFu, eB, 2);
        if ((lane & 3) == 0) {
            int rowA = wm * 64 + mi * 16 + (lane >> 2);       // 0..255
            rs[wn * 256 + rowA] = eA;
            rs[wn * 256 + rowA + 8] = eB;
        }
    }
    __syncthreads();
    if (tid < 256) {
        float s = rs[tid] + rs[256 + tid];
        g_partial[(size_t)tid * 128 + blockIdx.x] = s;        // [row][ctaX]
    }

    // ---- grid barrier: all 128 CTAs co-resident (one wave) ----
    __threadfence();
    __syncthreads();
    if (tid == 0) {
        atomicAdd(&g_done, 1u);
        while (atomicAdd(&g_done, 0u) < (unsigned)gridDim.x)
            __nanosleep(128);
    }
    __syncthreads();

    // ---- phase C: lse + pair mining for rows 2b, 2b+1 ----
    TailSmem* T = (TailSmem*)smem;
    T->idx[tid] = indexs[tid];
    __syncthreads();
    do_row(blockIdx.x * 2, T, outp, inp, targets, ppairs, npairs, cluster,
           out, offset, tid, lane, warp);
    __syncthreads();
    do_row(blockIdx.x * 2 + 1, T, outp, inp, targets, ppairs, npairs, cluster,
           out, offset, tid, lane, warp);
}

// ---------------- launch ----------------
extern "C" void kernel_launch(void* const* d_in, const int* in_sizes, int n_in,
                              void* d_out, int out_size) {
    const float* inputs  = (const float*)d_in[0];
    const int*   targets = (const int*)d_in[1];
    const int*   ppairs  = (const int*)d_in[2];
    const int*   npairs  = (const int*)d_in[3];
    const int*   indexs  = (const int*)d_in[4];
    const int*   cluster = (const int*)d_in[5];
    const float* V       = (const float*)d_in[6];
    // d_in[7] = epoch (unused)

    float* out = (float*)d_out;
    int offset = out_size - B * C;
    if (offset < 0) offset = 0;
    float* outputs = out + offset;   // logits live in the output buffer

    cudaFuncSetAttribute(fused_kernel,
                         cudaFuncAttributeMaxDynamicSharedMemorySize, GEMM_SMEM);

    fused_kernel<<<C / GBN, 256, GEMM_SMEM>>>(
        inputs, V, outputs, targets, ppairs, npairs, indexs, cluster,
        out, offset);
}

// round 17
// speedup vs baseline: 1.1153x; 1.1153x over previous
#include <cuda_runtime.h>
#include <math.h>
#include <stdint.h>

// Problem constants (from reference)
#define B   256
#define F   2048
#define C   16384
#define NS  65536
#define P   8
#define NN  32
#define P_MARGIN 0.1f
#define N_MARGIN 0.1f
#define W_H 10.0

// tf32 truncation bias compensation: 2*ln2*2^-11
#define TF32_COMP 1.000677f
#define LSE_SHIFT 8.0f

// ---------------- device scratch (no allocations allowed) ----------------
__device__ float    g_partial[B * 128];   // [row][ctaX] partial sums of exp(x-8)
__device__ double   g_hp_sum;
__device__ double   g_hn_sum;
__device__ double   g_bu_sum;
__device__ unsigned g_ticket;

__device__ __forceinline__ uint32_t smem_u32(const void* p) {
    uint32_t a;
    asm("{ .reg .u64 t; cvta.to.shared.u64 t, %1; cvt.u32.u64 %0, t; }" : "=r"(a) : "l"(p));
    return a;
}
__device__ __forceinline__ uint32_t swz128(uint32_t x) { return x ^ ((x >> 3) & 0x70); }
__device__ __forceinline__ void cpasync16(uint32_t s, const void* g) {
    asm volatile("cp.async.cg.shared.global [%0], [%1], 16;" :: "r"(s), "l"(g));
}

// =====================================================================
//  tf32 mma.sync GEMM + fused softmax-partials epilogue (round-15 exact:
//  256x128x64 CTA tile, 64x64 warp tile, 2-stage GBK=64 pipeline,
//  single-buffered fragments, ~190 regs — do NOT co-compile tails here;
//  round 16 showed that pushes regs to 254 and slows the mainloop).
//  NOTE: outp is only 4-byte aligned (out + 1) -> scalar stores ONLY.
// =====================================================================
#define GBM 256
#define GBN 128
#define GBK 64
#define GSTAGES 2
#define A_HALF  (GBM * 128)              // 32 KB (one k-half of A)
#define B_HALF  (GBN * 128)              // 16 KB
#define A_BYTES (2 * A_HALF)             // 64 KB
#define B_BYTES (2 * B_HALF)             // 32 KB
#define STG_B   (A_BYTES + B_BYTES)      // 96 KB
#define GEMM_SMEM (GSTAGES * STG_B)      // 192 KB
#define NCHUNK  (F / GBK)                // 32

__device__ __forceinline__ void ldsm_x4(uint32_t addr, uint32_t* r) {
    asm volatile("ldmatrix.sync.aligned.m8n8.x4.shared.b16 {%0,%1,%2,%3}, [%4];"
                 : "=r"(r[0]), "=r"(r[1]), "=r"(r[2]), "=r"(r[3]) : "r"(addr));
}

__device__ __forceinline__ void load_stage_g(uint32_t sbase, int s, int chunk,
                                             const float* __restrict__ inp,
                                             const float* __restrict__ Vm,
                                             int nbase, int tid) {
    const int kbase = chunk * GBK;
    const uint32_t sA = sbase + s * STG_B;
    const uint32_t sB = sA + A_BYTES;
#pragma unroll
    for (int i = 0; i < 16; i++) {           // A: 256 rows x 64 floats
        int id = tid + i * 256;
        int row = id >> 4, c4 = id & 15;
        uint32_t half = (uint32_t)(c4 >> 3) * A_HALF;
        int c4in = c4 & 7;
        cpasync16(sA + half + swz128(row * 128 + c4in * 16),
                  inp + (size_t)row * F + kbase + c4 * 4);
    }
#pragma unroll
    for (int i = 0; i < 8; i++) {            // B: 128 rows x 64 floats
        int id = tid + i * 256;
        int row = id >> 4, c4 = id & 15;
        uint32_t half = (uint32_t)(c4 >> 3) * B_HALF;
        int c4in = c4 & 7;
        cpasync16(sB + half + swz128(row * 128 + c4in * 16),
                  Vm + (size_t)(nbase + row) * F + kbase + c4 * 4);
    }
}

__global__ __launch_bounds__(256, 1) void gemm_mma_kernel(
        const float* __restrict__ inp,       // [B, F]
        const float* __restrict__ Vm,        // [C, F]
        float* __restrict__ outp) {          // [B, C] (4-byte aligned only!)
    extern __shared__ __align__(1024) char smem[];
    const uint32_t sbase = smem_u32(smem);
    const int tid = threadIdx.x;
    const int nbase = blockIdx.x * GBN;
    const int lane = tid & 31;
    const int warp = tid >> 5;
    const int wm = warp >> 1;                // 0..3 -> m offset 64*wm
    const int wn = warp & 1;                 // 0..1 -> n offset 64*wn

    // reset global accumulators (gemm strictly precedes lsepairs in stream)
    if (blockIdx.x == 0 && tid == 0) {
        g_hp_sum = 0.0;
        g_hn_sum = 0.0;
        g_bu_sum = 0.0;
        g_ticket = 0u;
    }

    float acc[4][8][4];
#pragma unroll
    for (int mi = 0; mi < 4; mi++)
#pragma unroll
        for (int ni = 0; ni < 8; ni++)
#pragma unroll
            for (int j = 0; j < 4; j++) acc[mi][ni][j] = 0.f;

    // prologue: 1 chunk in flight
    load_stage_g(sbase, 0, 0, inp, Vm, nbase, tid);
    asm volatile("cp.async.commit_group;" ::: "memory");

    // per-lane ldmatrix row components
    const int a_row_lo = (lane & 8) + (lane & 7);
    const int a_chunk_off = lane >> 4;
    const int b_row8 = lane & 7;
    const int b_ni_off = lane >> 4;
    const int b_chunk_off = (lane >> 3) & 1;

    for (int c = 0; c < NCHUNK; c++) {
        asm volatile("cp.async.wait_group 0;" ::: "memory");
        __syncthreads();

        if (c + 1 < NCHUNK) {
            load_stage_g(sbase, (c + 1) & 1, c + 1, inp, Vm, nbase, tid);
            asm volatile("cp.async.commit_group;" ::: "memory");
        }

        const uint32_t aS = sbase + (c & 1) * STG_B;
        const uint32_t bS = aS + A_BYTES;
#pragma unroll
        for (int ks = 0; ks < 8; ks++) {
            const uint32_t aSh = aS + (uint32_t)(ks >> 2) * A_HALF;
            const uint32_t bSh = bS + (uint32_t)(ks >> 2) * B_HALF;
            const int ksl = ks & 3;
            uint32_t af[4][4];
#pragma unroll
            for (int mi = 0; mi < 4; mi++) {
                int row = wm * 64 + mi * 16 + a_row_lo;
                int chunk = ksl * 2 + a_chunk_off;
                uint32_t addr = aSh + row * 128 + (((uint32_t)(chunk ^ (row & 7))) << 4);
                ldsm_x4(addr, af[mi]);
            }
            uint32_t bf[8][2];
#pragma unroll
            for (int bp = 0; bp < 4; bp++) {
                int ni = bp * 2 + b_ni_off;
                int row = wn * 64 + ni * 8 + b_row8;
                int chunk = ksl * 2 + b_chunk_off;
                uint32_t addr = bSh + row * 128 + (((uint32_t)(chunk ^ (row & 7))) << 4);
                uint32_t r[4];
                ldsm_x4(addr, r);
                bf[bp * 2][0] = r[0];     bf[bp * 2][1] = r[1];
                bf[bp * 2 + 1][0] = r[2]; bf[bp * 2 + 1][1] = r[3];
            }
            // no cvt: HW truncates fp32 -> tf32; compensated in epilogue
#pragma unroll
            for (int mi = 0; mi < 4; mi++)
#pragma unroll
                for (int ni = 0; ni < 8; ni++) {
                    asm volatile(
                        "mma.sync.aligned.m16n8k8.row.col.f32.tf32.tf32.f32 "
                        "{%0,%1,%2,%3}, {%4,%5,%6,%7}, {%8,%9}, {%0,%1,%2,%3};"
                        : "+f"(acc[mi][ni][0]), "+f"(acc[mi][ni][1]),
                          "+f"(acc[mi][ni][2]), "+f"(acc[mi][ni][3])
                        : "r"(af[mi][0]), "r"(af[mi][1]),
                          "r"(af[mi][2]), "r"(af[mi][3]),
                          "r"(bf[ni][0]), "r"(bf[ni][1]));
                }
        }
    }

    // ---- epilogue 1: compensated logits -> gmem (scalar stores, 4B align) ----
#pragma unroll
    for (int mi = 0; mi < 4; mi++) {
#pragma unroll
        for (int ni = 0; ni < 8; ni++) {
            int m = wm * 64 + mi * 16 + (lane >> 2);
            int n = nbase + wn * 64 + ni * 8 + 2 * (lane & 3);
            float* p0 = outp + (size_t)m * C + n;
            float* p1 = outp + (size_t)(m + 8) * C + n;
#pragma unroll
            for (int j = 0; j < 4; j++) acc[mi][ni][j] *= TF32_COMP;
            p0[0] = acc[mi][ni][0];
            p0[1] = acc[mi][ni][1];
            p1[0] = acc[mi][ni][2];
            p1[1] = acc[mi][ni][3];
        }
    }

    // ---- epilogue 2: per-CTA exp-sum partials (deterministic) ----
    __syncthreads();                         // all ldsm reads of smem done
    float* rs = (float*)smem;                // rs[2][256] (wn-sliced row sums)
#pragma unroll
    for (int mi = 0; mi < 4; mi++) {
        float eA = 0.f, eB = 0.f;
#pragma unroll
        for (int ni = 0; ni < 8; ni++) {
            eA += __expf(acc[mi][ni][0] - LSE_SHIFT) + __expf(acc[mi][ni][1] - LSE_SHIFT);
            eB += __expf(acc[mi][ni][2] - LSE_SHIFT) + __expf(acc[mi][ni][3] - LSE_SHIFT);
        }
        eA += __shfl_xor_sync(0xFFFFFFFFu, eA, 1);
        eA += __shfl_xor_sync(0xFFFFFFFFu, eA, 2);
        eB += __shfl_xor_sync(0xFFFFFFFFu, eB, 1);
        eB += __shfl_xor_sync(0xFFFFFFFFu, eB, 2);
        if ((lane & 3) == 0) {
            int rowA = wm * 64 + mi * 16 + (lane >> 2);       // 0..255
            rs[wn * 256 + rowA] = eA;
            rs[wn * 256 + rowA + 8] = eB;
        }
    }
    __syncthreads();
    if (tid < 256) {
        float s = rs[tid] + rs[256 + tid];
        g_partial[(size_t)tid * 128 + blockIdx.x] = s;        // [row][ctaX]
    }
}

// =====================================================================
//  Fused: lse from partials + on-demand pair dots + parallel mining +
//  final loss. 256 blocks (one per row) x 256 threads.
//  Candidate matching INVERTED: instead of 40 threads serially scanning
//  256 indexs (a ~7k-cycle LDS chain), all 256 threads compare their own
//  indexs[tid] against the 40 staged candidate values (40-iter loop).
// =====================================================================
#define NCAND 40            // 8 ppairs + 32 npairs
__global__ __launch_bounds__(256) void lsepairs_kernel(
        const float* __restrict__ outputs,
        const float* __restrict__ inputs,
        const int* __restrict__ targets,
        const int* __restrict__ ppairs,
        const int* __restrict__ npairs,
        const int* __restrict__ indexs,
        const int* __restrict__ cluster,
        float* __restrict__ out, int offset) {
    const int row = blockIdx.x;
    const int tid = threadIdx.x;
    const int lane = tid & 31;
    const int warp = tid >> 5;
    const float* x = outputs + (size_t)row * C;

    __shared__ float s_xi[F];            // this row of inputs (8 KB)
    __shared__ float red[128];
    __shared__ int   s_m[NCAND];         // matched batch idx, -1 = unmatched
    __shared__ int   s_v[NCAND];         // raw candidate value
    __shared__ float s_dij[NCAND + 1];   // dot(x_i, x_j); [40] = dot(x_i, x_i)
    __shared__ float s_djj[NCAND + 1];   // dot(x_j, x_j)
    __shared__ float s_tn[NN];           // table negative logits
    __shared__ float s_tp;               // target logit
    __shared__ float s_lse;
    __shared__ float s_ps[P + 1];
    __shared__ int   s_pm[P + 1];
    __shared__ float s_ns[2 * NN];
    __shared__ int   s_nm[2 * NN];

    // phase 1: stage row i, partials, candidate values
    {
        const float4* xi4 = (const float4*)(inputs + (size_t)row * F);
        float4* s4 = (float4*)s_xi;
        s4[tid] = xi4[tid];
        s4[tid + 256] = xi4[tid + 256];
    }
    const int myidx = indexs[tid];       // per-thread batch index value
    if (tid < 128) red[tid] = g_partial[(size_t)row * 128 + tid];
    if (tid >= 128 && tid < 128 + NCAND) {
        int c = tid - 128;
        int v = (c < P) ? ppairs[row * P + c] : npairs[row * NN + (c - P)];
        s_v[c] = v;
        s_m[c] = -1;
    } else if (tid >= 192 && tid < 192 + NN) {
        int k = tid - 192;
        int v = npairs[row * NN + k];
        int vc = v > 0 ? v : 0;
        s_tn[k] = x[cluster[vc]];
    } else if (tid == 192 + NN) {
        s_tp = x[targets[row]];
    }
    __syncthreads();

    // phase 2: inverted parallel candidate match (each thread vs 40 cands)
#pragma unroll
    for (int c = 0; c < NCAND; c++) {
        if (s_v[c] == myidx) s_m[c] = tid;   // indexs unique -> 1 writer max
    }
    // lse (warp 0) overlapped with match
    if (tid < 32) {
        float s = red[lane] + red[lane + 32] + red[lane + 64] + red[lane + 96];
#pragma unroll
        for (int st = 16; st > 0; st >>= 1)
            s += __shfl_xor_sync(0xFFFFFFFFu, s, st);
        if (lane == 0) s_lse = logf(s) + LSE_SHIFT;
    }
    __syncthreads();

    // phase 3: warp-per-pair dot products (8 warps)
    for (int c = warp; c <= NCAND; c += 8) {
        int j = (c == NCAND) ? row : s_m[c];
        if (j < 0) { if (lane == 0) { s_dij[c] = 0.f; s_djj[c] = 1.f; } continue; }
        const float4* xj4 = (const float4*)(inputs + (size_t)j * F);
        const float4* xi4 = (const float4*)s_xi;
        float sij = 0.f, sjj = 0.f;
#pragma unroll 4
        for (int t = lane; t < F / 4; t += 32) {
            float4 bv = xj4[t];
            float4 av = xi4[t];
            sij += av.x * bv.x + av.y * bv.y + av.z * bv.z + av.w * bv.w;
            sjj += bv.x * bv.x + bv.y * bv.y + bv.z * bv.z + bv.w * bv.w;
        }
#pragma unroll
        for (int st = 16; st > 0; st >>= 1) {
            sij += __shfl_xor_sync(0xFFFFFFFFu, sij, st);
            sjj += __shfl_xor_sync(0xFFFFFFFFu, sjj, st);
        }
        if (lane == 0) { s_dij[c] = sij; s_djj[c] = sjj; }
    }
    __syncthreads();

    // phase 4: candidate sims (parallel fill of ps/ns in smem)
    {
        const float inorm = sqrtf(s_djj[NCAND]);
        if (tid < P) {
            int idx = s_m[tid];
            s_pm[tid] = (idx >= 0);
            s_ps[tid] = (idx >= 0) ? s_dij[tid] / (inorm * sqrtf(s_djj[tid])) : 0.f;
        } else if (tid == P) {
            float tp = s_tp / inorm;
            s_ps[P] = tp;
            s_pm[P] = (tp != 0.0f);
        } else if (tid >= 32 && tid < 32 + NN) {
            int k = tid - 32;
            int c = P + k;
            int idx = s_m[c];
            s_nm[k] = (idx >= 0);
            s_ns[k] = (idx >= 0) ? s_dij[c] / (inorm * sqrtf(s_djj[c])) : 0.f;
        } else if (tid >= 64 && tid < 64 + NN) {
            int k = tid - 64;
            float tn = s_tn[k] / inorm;
            s_ns[NN + k] = tn;
            s_nm[NN + k] = ((s_v[P + k] >= 0) && (tn != 0.0f));
        }
    }
    __syncthreads();

    // phase 5: warp-0 mining via shfl reductions
    if (tid < 32) {
        int m0 = s_nm[lane], m1 = s_nm[lane + 32];
        float v0 = s_ns[lane], v1 = s_ns[lane + 32];
        float nmax = fmaxf(m0 ? v0 : -INFINITY, m1 ? v1 : -INFINITY);
#pragma unroll
        for (int st = 16; st > 0; st >>= 1)
            nmax = fmaxf(nmax, __shfl_xor_sync(0xFFFFFFFFu, nmax, st));
        int anyn = __ballot_sync(0xFFFFFFFFu, m0 || m1) != 0;
        float p_thrd = (anyn ? nmax : -3.0f) + P_MARGIN;

        int pmv = (lane < P + 1) ? s_pm[lane] : 0;
        float pv = pmv ? s_ps[lane] : INFINITY;
        float pmin = pv;
#pragma unroll
        for (int st = 16; st > 0; st >>= 1)
            pmin = fminf(pmin, __shfl_xor_sync(0xFFFFFFFFu, pmin, st));
        int anyp = __ballot_sync(0xFFFFFFFFu, pmv) != 0;
        float n_thrd = (anyp ? pmin : 3.0f) - N_MARGIN;

        double hp = 0.0, hn = 0.0;
        if (pmv && pv < p_thrd) hp = (double)expf(-2.0f * (pv - 0.5f));
        if (m0 && v0 > n_thrd && v0 < 0.999999f) hn += (double)expf(50.0f * (v0 - 0.5f));
        if (m1 && v1 > n_thrd && v1 < 0.999999f) hn += (double)expf(50.0f * (v1 - 0.5f));
#pragma unroll
        for (int st = 16; st > 0; st >>= 1) {
            hp += __shfl_xor_sync(0xFFFFFFFFu, hp, st);
            hn += __shfl_xor_sync(0xFFFFFFFFu, hn, st);
        }

        if (lane == 0) {
            if (hp != 0.0) atomicAdd(&g_hp_sum, hp);
            if (hn != 0.0) atomicAdd(&g_hn_sum, hn);
            atomicAdd(&g_bu_sum, (double)(s_lse - s_tp));
            __threadfence();
            unsigned ticket = atomicAdd(&g_ticket, 1u);
            if (ticket == B - 1) {
                double bu = g_bu_sum / (double)B;
                double hp_loss = (g_hp_sum > 0.0) ? 0.5 * log1p(g_hp_sum) : 0.0;
                double hn_loss = (g_hn_sum > 0.0) ? (1.0 / 50.0) * log1p(g_hn_sum) : 0.0;
                float loss = (float)(bu + W_H * (hp_loss + hn_loss));
                for (int i = 0; i < offset; i++) out[i] = loss;
            }
        }
    }
}

// ---------------- launch ----------------
extern "C" void kernel_launch(void* const* d_in, const int* in_sizes, int n_in,
                              void* d_out, int out_size) {
    const float* inputs  = (const float*)d_in[0];
    const int*   targets = (const int*)d_in[1];
    const int*   ppairs  = (const int*)d_in[2];
    const int*   npairs  = (const int*)d_in[3];
    const int*   indexs  = (const int*)d_in[4];
    const int*   cluster = (const int*)d_in[5];
    const float* V       = (const float*)d_in[6];
    // d_in[7] = epoch (unused)

    float* out = (float*)d_out;
    int offset = out_size - B * C;
    if (offset < 0) offset = 0;
    float* outputs = out + offset;   // logits live in the output buffer

    cudaFuncSetAttribute(gemm_mma_kernel,
                         cudaFuncAttributeMaxDynamicSharedMemorySize, GEMM_SMEM);

    // outputs = inputs @ V^T via mma.sync tf32; fused exp-sum partials
    gemm_mma_kernel<<<C / GBN, 256, GEMM_SMEM>>>(inputs, V, outputs);

    // lse from partials + on-demand pair dots + mining + final loss
    lsepairs_kernel<<<B, 256>>>(outputs, inputs, targets, ppairs, npairs,
                                indexs, cluster, out, offset);
}